// round 9
// baseline (speedup 1.0000x reference)
#include <cuda_runtime.h>
#include <cuda_bf16.h>
#include <math.h>
#include <string.h>

// support [25,2560] f32, query [4096,2560] f32 -> out [4096,5] f32
#define D       2560
#define NS      25
#define NSB     26              // 25 supports + 1 ones-row (gives qsum)
#define NPAD    32
#define NQ      4096
#define NWAY    5
#define KSHOT   5
#define EPSV    1e-6f

#define NSPLIT  8
#define DQ      320             // K per CTA
#define MROWS   128             // query rows per CTA
#define NRB     32              // NQ / MROWS
#define THREADS 256
#define BSTRIDE 328             // bf16 elems per B smem row (conflict-free)

#define KSUB    32              // f32 cols per cp.async stage
#define NSTG    10              // DQ / KSUB
#define ST      4               // ring depth
#define QSTRIDE 36              // padded f32 row stride
#define STAGEF  (MROWS * QSTRIDE)
#define DSMEM   (ST * STAGEF * 4)   // dynamic smem bytes (73728)

typedef unsigned long long u64;

__device__ float g_dot[NSPLIT][NRB][NSB][MROWS];
__device__ float g_qn [NSPLIT][NRB][MROWS];
__device__ float g_sn [NSPLIT][NS];
__device__ int   g_ctr[NRB];    // zero-init; self-resetting per launch

__device__ __forceinline__ u64 ffma2(u64 a, u64 b, u64 c) {
    u64 d;
    asm("fma.rn.f32x2 %0, %1, %2, %3;" : "=l"(d) : "l"(a), "l"(b), "l"(c));
    return d;
}
__device__ __forceinline__ float f2_sum(u64 v) {
    return __uint_as_float((unsigned)(v & 0xffffffffull)) +
           __uint_as_float((unsigned)(v >> 32));
}
__device__ __forceinline__ u64 as_u64(float2 v) {
    u64 r; memcpy(&r, &v, 8); return r;
}
__device__ __forceinline__ unsigned cvt_bf2(float2 v) {
    __nv_bfloat162 p = __floats2bfloat162_rn(v.x, v.y);
    unsigned r; memcpy(&r, &p, 4); return r;
}
__device__ __forceinline__ void mma16816(float c[4],
                                         unsigned a0, unsigned a1,
                                         unsigned a2, unsigned a3,
                                         unsigned b0, unsigned b1) {
    asm volatile(
        "mma.sync.aligned.m16n8k16.row.col.f32.bf16.bf16.f32 "
        "{%0,%1,%2,%3}, {%4,%5,%6,%7}, {%8,%9}, {%0,%1,%2,%3};"
        : "+f"(c[0]), "+f"(c[1]), "+f"(c[2]), "+f"(c[3])
        : "r"(a0), "r"(a1), "r"(a2), "r"(a3), "r"(b0), "r"(b1));
}

// ---------------------------------------------------------------------------
// CTA = (row block rb, K-eighth qd), 2 CTAs/SM. Warp owns 16 query rows.
// Query streamed through a 4-stage cp.async ring (raw f32, padded rows);
// A fragments built by LDS + in-register f32->bf16 cvt. B (support bf16)
// staged once; row 25 = ones so the MMA emits sum(q~) for free.
// ---------------------------------------------------------------------------
__global__ __launch_bounds__(THREADS, 2)
void pd_mma(const float* __restrict__ support,
            const float* __restrict__ query,
            float* __restrict__ out) {
    extern __shared__ float Qs[];                 // [ST][MROWS][QSTRIDE]
    __shared__ __align__(16) __nv_bfloat16 Bs[NPAD][BSTRIDE];
    __shared__ float s_red[NS][8][2];
    __shared__ float s_sn[NS];
    __shared__ int   s_flag;

    const int tid  = threadIdx.x;
    const int warp = tid >> 5;
    const int ln   = tid & 31;
    const int gid  = ln >> 2;
    const int tig  = ln & 3;
    const int rb   = blockIdx.x;
    const int qd   = blockIdx.y;
    const int dstart = qd * DQ;

    // ---- cp.async stage issue (4 x 16B per thread), always commits ----
    const float* qbase_g = query + (size_t)rb * MROWS * D + dstart;
    auto issue_stage = [&](int st) {
        if (st < NSTG) {
            float* buf = Qs + (st & (ST - 1)) * STAGEF;
            const float* srcb = qbase_g + st * KSUB;
            #pragma unroll
            for (int k = 0; k < 4; ++k) {
                const int i   = tid + k * THREADS;
                const int row = i >> 3;
                const int seg = i & 7;
                const float* src = srcb + (size_t)row * D + seg * 4;
                const unsigned dst = (unsigned)__cvta_generic_to_shared(
                    buf + row * QSTRIDE + seg * 4);
                asm volatile("cp.async.cg.shared.global [%0], [%1], 16;"
                             :: "r"(dst), "l"(src));
            }
        }
        asm volatile("cp.async.commit_group;");
    };

    // prologue: start filling stages 0..2 before doing anything else
    issue_stage(0); issue_stage(1); issue_stage(2);

    // ---- ones row (25) and zero pad rows (26..31) ----
    for (int i = tid; i < (NPAD - NS) * BSTRIDE; i += THREADS) {
        const int r = NS + i / BSTRIDE;
        const int c = i % BSTRIDE;
        Bs[r][c] = __float2bfloat16(r == NS ? 1.f : 0.f);
    }

    // ---- stage B: 25x320 f32 -> bf16 (rounded), plus ssq/ssm partials ----
    if (tid < NS * 8) {
        const int n  = tid >> 3;
        const int kc = tid & 7;                    // 40-col strip
        const float* src = support + (size_t)n * D + dstart + kc * 40;
        float ssq = 0.f, ssm = 0.f;
        #pragma unroll
        for (int j = 0; j < 10; ++j) {
            const float4 v = *reinterpret_cast<const float4*>(src + j * 4);
            const __nv_bfloat162 p0 = __floats2bfloat162_rn(v.x, v.y);
            const __nv_bfloat162 p1 = __floats2bfloat162_rn(v.z, v.w);
            const float r0 = __bfloat162float(p0.x), r1 = __bfloat162float(p0.y);
            const float r2 = __bfloat162float(p1.x), r3 = __bfloat162float(p1.y);
            ssq = fmaf(r0, r0, ssq); ssq = fmaf(r1, r1, ssq);
            ssq = fmaf(r2, r2, ssq); ssq = fmaf(r3, r3, ssq);
            ssm += (r0 + r1) + (r2 + r3);
            u64 u; memcpy(&u, &p0, 4); memcpy(((char*)&u) + 4, &p1, 4);
            *reinterpret_cast<u64*>(&Bs[n][kc * 40 + j * 4]) = u;
        }
        s_red[n][kc][0] = ssq;
        s_red[n][kc][1] = ssm;
    }
    __syncthreads();
    if (tid < NS) {
        float a = 0.f, b = 0.f;
        #pragma unroll
        for (int o = 0; o < 8; ++o) { a += s_red[tid][o][0]; b += s_red[tid][o][1]; }
        g_sn[qd][tid] = a + 2.f * EPSV * b;   // ||s~||^2 + 2 eps sum(s~) (eighth)
    }

    // ---- mainloop: 10 stages x 2 k16-chunks ----
    const int lrow = warp * 16 + gid;          // this thread's query row
    float c[4][4];
    #pragma unroll
    for (int nt = 0; nt < 4; ++nt)
        #pragma unroll
        for (int i = 0; i < 4; ++i) c[nt][i] = 0.f;
    u64 qn0 = 0ull, qn1 = 0ull;
    const __nv_bfloat16* brow = &Bs[gid][tig * 2];
    const int qoff = lrow * QSTRIDE + tig * 2; // FIX: use lrow, not gid

    for (int st = 0; st < NSTG; ++st) {
        asm volatile("cp.async.wait_group 2;");
        __syncthreads();
        const float* buf = Qs + (st & (ST - 1)) * STAGEF + qoff;
        #pragma unroll
        for (int c01 = 0; c01 < 2; ++c01) {
            const float* qp = buf + c01 * 16;
            const float2 a0 = *reinterpret_cast<const float2*>(qp);
            const float2 a2 = *reinterpret_cast<const float2*>(qp + 8);
            const float2 a1 = *reinterpret_cast<const float2*>(qp + 8 * QSTRIDE);
            const float2 a3 = *reinterpret_cast<const float2*>(qp + 8 * QSTRIDE + 8);
            qn0 = ffma2(as_u64(a0), as_u64(a0), qn0);
            qn0 = ffma2(as_u64(a2), as_u64(a2), qn0);
            qn1 = ffma2(as_u64(a1), as_u64(a1), qn1);
            qn1 = ffma2(as_u64(a3), as_u64(a3), qn1);
            const unsigned ra0 = cvt_bf2(a0);
            const unsigned ra1 = cvt_bf2(a1);
            const unsigned ra2 = cvt_bf2(a2);
            const unsigned ra3 = cvt_bf2(a3);
            const int k0 = st * KSUB + c01 * 16;
            #pragma unroll
            for (int nt = 0; nt < 4; ++nt) {
                const __nv_bfloat16* bp = brow + nt * 8 * BSTRIDE + k0;
                const unsigned b0 = *reinterpret_cast<const unsigned*>(bp);
                const unsigned b1 = *reinterpret_cast<const unsigned*>(bp + 8);
                mma16816(c[nt], ra0, ra1, ra2, ra3, b0, b1);
            }
        }
        __syncthreads();          // stage fully consumed before ring reuse
        issue_stage(st + ST - 1); // refill (empty commit past the end)
    }

    // ---- qn: reduce over the 4 quad lanes (same row) ----
    float q0 = f2_sum(qn0), q1 = f2_sum(qn1);
    q0 += __shfl_xor_sync(0xffffffffu, q0, 1);
    q0 += __shfl_xor_sync(0xffffffffu, q0, 2);
    q1 += __shfl_xor_sync(0xffffffffu, q1, 1);
    q1 += __shfl_xor_sync(0xffffffffu, q1, 2);
    if (tig == 0) {
        g_qn[qd][rb][lrow]     = q0;
        g_qn[qd][rb][lrow + 8] = q1;
    }

    // ---- publish dot partials ----
    #pragma unroll
    for (int nt = 0; nt < 4; ++nt) {
        const int s = nt * 8 + tig * 2;
        if (s < NSB) {
            g_dot[qd][rb][s][lrow]     = c[nt][0];
            g_dot[qd][rb][s][lrow + 8] = c[nt][2];
        }
        if (s + 1 < NSB) {
            g_dot[qd][rb][s + 1][lrow]     = c[nt][1];
            g_dot[qd][rb][s + 1][lrow + 8] = c[nt][3];
        }
    }

    __threadfence();
    __syncthreads();
    if (tid == 0) s_flag = atomicAdd(&g_ctr[rb], 1);
    __syncthreads();

    // ---- last CTA of this row block finishes ----
    if (s_flag == NSPLIT - 1) {
        if (tid < NS) {
            float a = 0.f;
            #pragma unroll
            for (int q = 0; q < NSPLIT; ++q) a += g_sn[q][tid];
            s_sn[tid] = a;
        }
        __syncthreads();
        if (tid < MROWS) {
            const int r = tid;
            float dt[NS];
            #pragma unroll
            for (int s = 0; s < NS; ++s) dt[s] = 0.f;
            float qnT = 0.f, qsT = 0.f;
            #pragma unroll
            for (int q = 0; q < NSPLIT; ++q) {
                #pragma unroll
                for (int s = 0; s < NS; ++s) dt[s] += g_dot[q][rb][s][r];
                qsT += g_dot[q][rb][25][r];     // ones-row dot = sum(q~)
                qnT += g_qn[q][rb][r];
            }
            // d2 = qn + (ssq + 2 eps ssm) + D eps^2 - 2 dot - 2 eps qsum
            const float base = qnT - 2.f * EPSV * qsT + (float)D * (EPSV * EPSV);
            #pragma unroll
            for (int w = 0; w < NWAY; ++w) {
                float sum = 0.f;
                #pragma unroll
                for (int k = 0; k < KSHOT; ++k) {
                    const int s = w * KSHOT + k;
                    const float d2 = base + s_sn[s] - 2.f * dt[s];
                    sum += sqrtf(fmaxf(d2, 0.f));
                }
                out[(size_t)(rb * MROWS + r) * NWAY + w] = -sum;
            }
        }
        if (tid == 0) g_ctr[rb] = 0;   // reset for next replay
    }
}

// ---------------------------------------------------------------------------
extern "C" void kernel_launch(void* const* d_in, const int* in_sizes, int n_in,
                              void* d_out, int out_size) {
    const float* support = (const float*)d_in[0];
    const float* query   = (const float*)d_in[1];
    if (n_in >= 2 && in_sizes[0] > in_sizes[1]) {
        const float* t = support; support = query; query = t;
    }
    float* out = (float*)d_out;

    cudaFuncSetAttribute(pd_mma, cudaFuncAttributeMaxDynamicSharedMemorySize,
                         DSMEM);
    pd_mma<<<dim3(NRB, NSPLIT), THREADS, DSMEM>>>(support, query, out);
}